// round 14
// baseline (speedup 1.0000x reference)
#include <cuda_runtime.h>
#include <cuda_bf16.h>

#define HOP   256
#define KUP   800
#define NMEL  80
#define RC    120
#define SC    240
#define NQ    256
#define NB    16
#define MAXL  40960
#define TT    128
#define NTH   512

// Scratch (device-global: sanctioned alternative to cudaMalloc)
static __device__ float g_cond[NMEL * MAXL];
static __device__ float g_res0[RC * MAXL];
static __device__ float g_res1[RC * MAXL];
static __device__ float g_skip[SC * MAXL];
static __device__ float g_y[NQ * MAXL];
// Pre-packed weights
static __device__ float4 g_wpk[NB * 120 * 120];   // (wt0,ws0,wt1,ws1) per (layer,pair,c)
static __device__ float4 g_qpk[NB * 120 * 40];    // (qt[c],qs[c],qt[c+1],qs[c+1])
static __device__ float2 g_bpk[NB * 192 * 120];   // (w_row2k[c], w_row2k+1[c]) pad 192
static __device__ float2 g_dpk1[128 * 240];       // h1 row-pairs
static __device__ float2 g_dpk2[128 * 256];       // h2 row-pairs

typedef unsigned long long ull;

// ---------------- packed f32x2 helpers (PTX-only FFMA2 path) ----------------
__device__ __forceinline__ ull pk2(float x, float y) {
    ull r;
    asm("mov.b64 %0, {%1,%2};" : "=l"(r) : "f"(x), "f"(y));
    return r;
}
__device__ __forceinline__ ull fma2(ull a, ull b, ull c) {
    ull d;
    asm("fma.rn.f32x2 %0, %1, %2, %3;" : "=l"(d) : "l"(a), "l"(b), "l"(c));
    return d;
}
__device__ __forceinline__ float2 up2(ull v) {
    float2 f;
    asm("mov.b64 {%0,%1}, %2;" : "=f"(f.x), "=f"(f.y) : "l"(v));
    return f;
}
__device__ __forceinline__ float gate(float zt, float zs) {
    return tanhf(zt) * (1.f / (1.f + __expf(-zs)));
}
// load 4 consecutive t from row base (16B aligned) and make 4 splats
__device__ __forceinline__ void splat4(ull* dst, const float* base) {
    float4 v = *(const float4*)base;
    dst[0] = pk2(v.x, v.x);
    dst[1] = pk2(v.y, v.y);
    dst[2] = pk2(v.z, v.z);
    dst[3] = pk2(v.w, v.w);
}

// ---------------- weight pre-pack -----------------------------------------------
__global__ void prepack_kernel(const float* __restrict__ bcw, const float* __restrict__ bqw,
                               const float* __restrict__ bsw, const float* __restrict__ brw,
                               const float* __restrict__ h1w, const float* __restrict__ h2w,
                               float4* __restrict__ wpk, float4* __restrict__ qpk,
                               float2* __restrict__ bpk, float2* __restrict__ dpk1,
                               float2* __restrict__ dpk2) {
    int idx = blockIdx.x * blockDim.x + threadIdx.x;
    const int W4 = NB * 120 * 120, Q4 = NB * 120 * 40, B2 = NB * 180 * 120;
    const int D1 = 128 * 240, D2 = 128 * 256;
    if (idx < W4) {
        int i = idx / (120 * 120), r = idx % (120 * 120), p = r / 120, c = r % 120;
        const float* cw = bcw + (size_t)i * SC * RC * 2;
        wpk[((size_t)i * 120 + p) * 120 + c] = make_float4(
            cw[(p * RC + c) * 2],     cw[((p + RC) * RC + c) * 2],
            cw[(p * RC + c) * 2 + 1], cw[((p + RC) * RC + c) * 2 + 1]);
    } else if (idx < W4 + Q4) {
        int k = idx - W4;
        int i = k / (120 * 40), r = k % (120 * 40), p = r / 40, cc = r % 40, c = cc * 2;
        const float* qw = bqw + (size_t)i * SC * NMEL;
        qpk[((size_t)i * 120 + p) * 40 + cc] = make_float4(
            qw[p * NMEL + c],     qw[(p + RC) * NMEL + c],
            qw[p * NMEL + c + 1], qw[(p + RC) * NMEL + c + 1]);
    } else if (idx < W4 + Q4 + B2) {
        int k = idx - W4 - Q4;
        int i = k / (180 * 120), r = k % (180 * 120), pr = r / 120, c = r % 120;
        float2 v;
        if (pr < 120) {
            const float* sw = bsw + (size_t)i * SC * RC;
            v = make_float2(sw[(2 * pr) * RC + c], sw[(2 * pr + 1) * RC + c]);
        } else {
            const float* rw = brw + (size_t)i * RC * RC;
            int q = pr - 120;
            v = make_float2(rw[(2 * q) * RC + c], rw[(2 * q + 1) * RC + c]);
        }
        bpk[((size_t)i * 192 + pr) * 120 + c] = v;
    } else if (idx < W4 + Q4 + B2 + D1) {
        int k = idx - W4 - Q4 - B2;
        int p = k / 240, c = k % 240;
        dpk1[p * 240 + c] = make_float2(h1w[(2 * p) * SC + c], h1w[(2 * p + 1) * SC + c]);
    } else if (idx < W4 + Q4 + B2 + D1 + D2) {
        int k = idx - W4 - Q4 - B2 - D1;
        int p = k / 256, c = k % 256;
        dpk2[p * 256 + c] = make_float2(h2w[(2 * p) * NQ + c], h2w[(2 * p + 1) * NQ + c]);
    }
}

// ---------------- cond upsampling: phase-major transposed conv ----------------
__global__ __launch_bounds__(256, 1)
void cond_kernel(const float* __restrict__ mel,
                 const float* __restrict__ upw,
                 const float* __restrict__ upb,
                 float* __restrict__ cond,
                 int L, int Tmel) {
    extern __shared__ float sm[];
    const int MS = Tmel + 8;
    float* smel = sm;
    float* sw   = sm + NMEL * MS;
    int tid = threadIdx.x;
    int p  = blockIdx.x;
    int k0 = 255 - p;

    for (int idx = tid; idx < NMEL * MS; idx += 256) {
        int c = idx / MS, col = idx - c * MS;
        smel[idx] = (col < Tmel) ? mel[c * Tmel + col] : 0.f;
    }
    for (int idx = tid; idx < NMEL * NMEL * 4; idx += 256) {
        int j = idx & 3;
        int oc = idx >> 2;
        int k = k0 + 256 * j;
        sw[idx] = (k < KUP) ? upw[oc * KUP + k] : 0.f;
    }
    __syncthreads();

    int nI = (L - p + 255) >> 8;
    int tx = tid & 7;
    int gy = tid >> 3;
    for (int o = gy; o < NMEL; o += 32) {
        float b = upb[o];
        for (int ib = 0; ib < nI; ib += 32) {
            int i0 = ib + tx * 4;
            float a0 = b, a1 = b, a2 = b, a3 = b;
            for (int c = 0; c < NMEL; c++) {
                const float4 w = *(const float4*)&sw[(o * NMEL + c) << 2];
                const float* mp = &smel[c * MS + i0 + 1];
                float m0 = mp[0], m1 = mp[1], m2 = mp[2], m3 = mp[3];
                float m4 = mp[4], m5 = mp[5], m6 = mp[6];
                a0 += w.x * m0 + w.y * m1 + w.z * m2 + w.w * m3;
                a1 += w.x * m1 + w.y * m2 + w.z * m3 + w.w * m4;
                a2 += w.x * m2 + w.y * m3 + w.z * m4 + w.w * m5;
                a3 += w.x * m3 + w.y * m4 + w.z * m5 + w.w * m6;
            }
            int t = p + (i0 << 8);
            if (i0     < nI) cond[o * L + t]       = a0;
            if (i0 + 1 < nI) cond[o * L + t + 256] = a1;
            if (i0 + 2 < nI) cond[o * L + t + 512] = a2;
            if (i0 + 3 < nI) cond[o * L + t + 768] = a3;
        }
    }
}

// ---------------- input 1x1 conv ----------------------------------------------
__global__ void init_kernel(const float* __restrict__ wav,
                            const float* __restrict__ inw,
                            const float* __restrict__ inb,
                            float* __restrict__ res, int L) {
    int idx = blockIdx.x * blockDim.x + threadIdx.x;
    if (idx >= RC * L) return;
    int c = idx / L, t = idx - c * L;
    res[idx] = inw[c] * wav[t] + inb[c];
}

// ---------------- fused WaveNet block: TT=128, 512 threads, t_lane=4 ------------
__global__ __launch_bounds__(NTH, 1)
void block_kernel(const float* __restrict__ rin,
                  float* __restrict__ rout,
                  float* __restrict__ skip,
                  const float* __restrict__ cond,
                  const float* __restrict__ wpk,  // [120][120][4]
                  const float* __restrict__ qpk,  // [120][40][4]
                  const float* __restrict__ bpk,  // [192][120][2]
                  const float* __restrict__ cb,
                  const float* __restrict__ qb,
                  const float* __restrict__ sbv,
                  const float* __restrict__ rb,
                  int d, int L, int first, int wres) {
    extern __shared__ float sm[];
    float* sA = sm;                 // res[c][t-d]  [120][128]
    float* sB = sA + RC * TT;       // res[c][t]    [120][128]
    float* sC = sB + RC * TT;       // cond[c][t]   [80][128]
    float* sH = sC + NMEL * TT;     // h[c][t]      [120][128]

    int tid = threadIdx.x;
    int t0 = blockIdx.x * TT;

    for (int idx = tid; idx < RC * TT; idx += NTH) {
        int c = idx >> 7, tl0 = idx & 127;
        int t = t0 + tl0;
        float vb = 0.f, va = 0.f;
        if (t < L) {
            vb = rin[c * L + t];
            int ta = t - d;
            if (ta >= 0) va = rin[c * L + ta];
        }
        sB[idx] = vb;
        sA[idx] = va;
    }
    for (int idx = tid; idx < NMEL * TT; idx += NTH) {
        int c = idx >> 7, tl0 = idx & 127;
        int t = t0 + tl0;
        sC[idx] = (t < L) ? cond[c * L + t] : 0.f;
    }
    __syncthreads();

    const int lid = tid & 31;
    const int wid = tid >> 5;    // 0..15
    const int tl  = 4 * lid;

    // ---- Phase A: 2 passes x 4 gate-pairs/warp; acc[j][k] = (zt@t_k, zs@t_k) ----
    #pragma unroll 1
    for (int pass = 0; pass < 2; pass++) {
        const int p0 = pass * 64 + wid * 4;
        if (p0 >= RC) break;
        ull z[4][4];
        #pragma unroll
        for (int j = 0; j < 4; j++) {
            int p = p0 + j < RC ? p0 + j : RC - 1;
            ull b0 = pk2(cb[p] + qb[p], cb[p + RC] + qb[p + RC]);
            z[j][0] = b0; z[j][1] = b0; z[j][2] = b0; z[j][3] = b0;
        }
        #pragma unroll 1
        for (int c = 0; c < RC; c += 2) {
            ull A0[4], B0[4], A1[4], B1[4];
            splat4(A0, &sA[c * TT + tl]);
            splat4(B0, &sB[c * TT + tl]);
            splat4(A1, &sA[(c + 1) * TT + tl]);
            splat4(B1, &sB[(c + 1) * TT + tl]);
            #pragma unroll
            for (int j = 0; j < 4; j++) {
                int p = p0 + j < RC ? p0 + j : RC - 1;
                const float* wr = wpk + (size_t)p * 480 + 4 * c;
                ulonglong2 w0 = *(const ulonglong2*)wr;        // c
                ulonglong2 w1 = *(const ulonglong2*)(wr + 4);  // c+1
                #pragma unroll
                for (int k = 0; k < 4; k++) {
                    z[j][k] = fma2(w0.x, A0[k], z[j][k]);
                    z[j][k] = fma2(w0.y, B0[k], z[j][k]);
                    z[j][k] = fma2(w1.x, A1[k], z[j][k]);
                    z[j][k] = fma2(w1.y, B1[k], z[j][k]);
                }
            }
        }
        #pragma unroll 1
        for (int c = 0; c < NMEL; c += 2) {
            ull C0[4], C1[4];
            splat4(C0, &sC[c * TT + tl]);
            splat4(C1, &sC[(c + 1) * TT + tl]);
            #pragma unroll
            for (int j = 0; j < 4; j++) {
                int p = p0 + j < RC ? p0 + j : RC - 1;
                ulonglong2 w = *(const ulonglong2*)(qpk + (size_t)p * 160 + 2 * c);
                #pragma unroll
                for (int k = 0; k < 4; k++) {
                    z[j][k] = fma2(w.x, C0[k], z[j][k]);
                    z[j][k] = fma2(w.y, C1[k], z[j][k]);
                }
            }
        }
        #pragma unroll
        for (int j = 0; j < 4; j++) {
            if (p0 + j >= RC) break;
            float4 h;
            float2 g0 = up2(z[j][0]);
            float2 g1 = up2(z[j][1]);
            float2 g2 = up2(z[j][2]);
            float2 g3 = up2(z[j][3]);
            h.x = gate(g0.x, g0.y);
            h.y = gate(g1.x, g1.y);
            h.z = gate(g2.x, g2.y);
            h.w = gate(g3.x, g3.y);
            *(float4*)&sH[(p0 + j) * TT + tl] = h;
        }
    }
    __syncthreads();

    // ---- Phase B: 3 passes x 4 row-pairs/warp; acc[j][k] = (row2k@t_k, row2k+1@t_k) ----
    #pragma unroll 1
    for (int pass = 0; pass < 3; pass++) {
        const int k0 = pass * 64 + wid * 4;
        if (k0 >= 180) break;
        ull z2[4][4];
        #pragma unroll
        for (int j = 0; j < 4; j++) {
            int k = k0 + j;
            int kk = k < 180 ? k : 179;
            float b1, b2;
            if (kk < 120) { b1 = sbv[2 * kk]; b2 = sbv[2 * kk + 1]; }
            else { b1 = rb[2 * (kk - 120)]; b2 = rb[2 * (kk - 120) + 1]; }
            ull bb = pk2(b1, b2);
            z2[j][0] = bb; z2[j][1] = bb; z2[j][2] = bb; z2[j][3] = bb;
        }
        #pragma unroll 1
        for (int c = 0; c < RC; c += 2) {
            ull H0[4], H1[4];
            splat4(H0, &sH[c * TT + tl]);
            splat4(H1, &sH[(c + 1) * TT + tl]);
            #pragma unroll
            for (int j = 0; j < 4; j++) {
                int kk = k0 + j < 180 ? k0 + j : 179;
                ulonglong2 w = *(const ulonglong2*)(bpk + (size_t)kk * 240 + 2 * c);
                #pragma unroll
                for (int k = 0; k < 4; k++) {
                    z2[j][k] = fma2(w.x, H0[k], z2[j][k]);
                    z2[j][k] = fma2(w.y, H1[k], z2[j][k]);
                }
            }
        }
        int t = t0 + tl;
        #pragma unroll
        for (int j = 0; j < 4; j++) {
            int k = k0 + j;
            if (k >= 180) break;
            float2 v0 = up2(z2[j][0]);
            float2 v1 = up2(z2[j][1]);
            float2 v2 = up2(z2[j][2]);
            float2 v3 = up2(z2[j][3]);
            float4 o1 = make_float4(v0.x, v1.x, v2.x, v3.x);  // row 2k, t..t+3
            float4 o2 = make_float4(v0.y, v1.y, v2.y, v3.y);  // row 2k+1
            if (k < 120) {
                int r1 = 2 * k;
                float* d1 = &skip[(size_t)r1 * L + t];
                float* d2 = &skip[(size_t)(r1 + 1) * L + t];
                if (t + 3 < L) {
                    if (first) { *(float4*)d1 = o1; *(float4*)d2 = o2; }
                    else {
                        float4 p1 = *(const float4*)d1, p2 = *(const float4*)d2;
                        o1.x += p1.x; o1.y += p1.y; o1.z += p1.z; o1.w += p1.w;
                        o2.x += p2.x; o2.y += p2.y; o2.z += p2.z; o2.w += p2.w;
                        *(float4*)d1 = o1; *(float4*)d2 = o2;
                    }
                } else {
                    float ov1[4] = {o1.x, o1.y, o1.z, o1.w};
                    float ov2[4] = {o2.x, o2.y, o2.z, o2.w};
                    #pragma unroll
                    for (int e = 0; e < 4; e++)
                        if (t + e < L) {
                            d1[e] = first ? ov1[e] : d1[e] + ov1[e];
                            d2[e] = first ? ov2[e] : d2[e] + ov2[e];
                        }
                }
            } else if (wres) {
                int rr = 2 * (k - 120);
                float4 s1 = *(const float4*)&sB[rr * TT + tl];
                float4 s2 = *(const float4*)&sB[(rr + 1) * TT + tl];
                o1.x += s1.x; o1.y += s1.y; o1.z += s1.z; o1.w += s1.w;
                o2.x += s2.x; o2.y += s2.y; o2.z += s2.z; o2.w += s2.w;
                float* d1 = &rout[(size_t)rr * L + t];
                float* d2 = &rout[(size_t)(rr + 1) * L + t];
                if (t + 3 < L) {
                    *(float4*)d1 = o1;
                    *(float4*)d2 = o2;
                } else {
                    float ov1[4] = {o1.x, o1.y, o1.z, o1.w};
                    float ov2[4] = {o2.x, o2.y, o2.z, o2.w};
                    #pragma unroll
                    for (int e = 0; e < 4; e++)
                        if (t + e < L) { d1[e] = ov1[e]; d2[e] = ov2[e]; }
                }
            }
        }
    }
}

// ---------------- dense head: TT=128, 512 threads, t_lane=4 ---------------------
__global__ __launch_bounds__(NTH, 1)
void dense_kernel(const float* __restrict__ x,
                  const float* __restrict__ dpk,  // [M/2][K][2]
                  const float* __restrict__ b,
                  float* __restrict__ out,
                  int L, int K, int M, int relu_in, int relu_out) {
    extern __shared__ float sm[];
    float* sX = sm;   // [K][128]
    int tid = threadIdx.x;
    int t0 = blockIdx.x * TT;
    for (int idx = tid; idx < K * TT; idx += NTH) {
        int c = idx >> 7, tl0 = idx & 127;
        int t = t0 + tl0;
        float v = (t < L) ? x[c * L + t] : 0.f;
        sX[idx] = relu_in ? fmaxf(v, 0.f) : v;
    }
    __syncthreads();

    const int lid = tid & 31;
    const int wid = tid >> 5;
    const int tl  = 4 * lid;
    const int MP = M / 2;   // pairs (128)

    #pragma unroll 1
    for (int pass = 0; pass * 64 < MP; pass++) {
        const int k0 = pass * 64 + wid * 4;
        if (k0 >= MP) break;
        ull z[4][4];
        #pragma unroll
        for (int j = 0; j < 4; j++) {
            int k = k0 + j;
            int kk = k < MP ? k : MP - 1;
            ull bb = pk2(b[2 * kk], b[2 * kk + 1]);
            z[j][0] = bb; z[j][1] = bb; z[j][2] = bb; z[j][3] = bb;
        }
        #pragma unroll 1
        for (int c = 0; c < K; c += 2) {
            ull X0[4], X1[4];
            splat4(X0, &sX[c * TT + tl]);
            splat4(X1, &sX[(c + 1) * TT + tl]);
            #pragma unroll
            for (int j = 0; j < 4; j++) {
                int kk = k0 + j < MP ? k0 + j : MP - 1;
                ulonglong2 w = *(const ulonglong2*)(dpk + ((size_t)kk * K + c) * 2);
                #pragma unroll
                for (int k = 0; k < 4; k++) {
                    z[j][k] = fma2(w.x, X0[k], z[j][k]);
                    z[j][k] = fma2(w.y, X1[k], z[j][k]);
                }
            }
        }
        int t = t0 + tl;
        #pragma unroll
        for (int j = 0; j < 4; j++) {
            int k = k0 + j;
            if (k >= MP) break;
            float2 v0 = up2(z[j][0]);
            float2 v1 = up2(z[j][1]);
            float2 v2 = up2(z[j][2]);
            float2 v3 = up2(z[j][3]);
            float4 o1 = make_float4(v0.x, v1.x, v2.x, v3.x);
            float4 o2 = make_float4(v0.y, v1.y, v2.y, v3.y);
            if (relu_out) {
                o1.x = fmaxf(o1.x, 0.f); o1.y = fmaxf(o1.y, 0.f);
                o1.z = fmaxf(o1.z, 0.f); o1.w = fmaxf(o1.w, 0.f);
                o2.x = fmaxf(o2.x, 0.f); o2.y = fmaxf(o2.y, 0.f);
                o2.z = fmaxf(o2.z, 0.f); o2.w = fmaxf(o2.w, 0.f);
            }
            float* d1 = &out[(size_t)(2 * k) * L + t];
            float* d2 = &out[(size_t)(2 * k + 1) * L + t];
            if (t + 3 < L) {
                *(float4*)d1 = o1;
                *(float4*)d2 = o2;
            } else {
                float ov1[4] = {o1.x, o1.y, o1.z, o1.w};
                float ov2[4] = {o2.x, o2.y, o2.z, o2.w};
                #pragma unroll
                for (int e = 0; e < 4; e++)
                    if (t + e < L) { d1[e] = ov1[e]; d2[e] = ov2[e]; }
            }
        }
    }
}

// ---------------- host launch ---------------------------------------------------
extern "C" void kernel_launch(void* const* d_in, const int* in_sizes, int n_in,
                              void* d_out, int out_size) {
    const float* wav  = (const float*)d_in[0];
    const float* mel  = (const float*)d_in[1];
    const float* up_w = (const float*)d_in[2];
    const float* up_b = (const float*)d_in[3];
    const float* in_w = (const float*)d_in[4];
    const float* in_b = (const float*)d_in[5];
    const float* bcw  = (const float*)d_in[6];
    const float* bcb  = (const float*)d_in[7];
    const float* bqw  = (const float*)d_in[8];
    const float* bqb  = (const float*)d_in[9];
    const float* bsw  = (const float*)d_in[10];
    const float* bsb  = (const float*)d_in[11];
    const float* brw  = (const float*)d_in[12];
    const float* brb  = (const float*)d_in[13];
    const float* h1w  = (const float*)d_in[14];
    const float* h1b  = (const float*)d_in[15];
    const float* h2w  = (const float*)d_in[16];
    const float* h2b  = (const float*)d_in[17];
    float* out = (float*)d_out;

    int wav_len = in_sizes[0];
    int Tmel = in_sizes[1] / NMEL;
    int up_len = (Tmel - 1) * HOP + 1;
    int pad = KUP - 1 - (KUP + 4 * HOP - 1024);   // = -1
    int cond_len = up_len + 2 * pad - KUP + 1;
    int L = wav_len < cond_len ? wav_len : cond_len;
    if (L > MAXL) L = MAXL;

    float *cond, *res0, *res1, *skip, *yb;
    float4 *wpk, *qpk; float2 *bpk, *dpk1, *dpk2;
    cudaGetSymbolAddress((void**)&cond, g_cond);
    cudaGetSymbolAddress((void**)&res0, g_res0);
    cudaGetSymbolAddress((void**)&res1, g_res1);
    cudaGetSymbolAddress((void**)&skip, g_skip);
    cudaGetSymbolAddress((void**)&yb,   g_y);
    cudaGetSymbolAddress((void**)&wpk,  g_wpk);
    cudaGetSymbolAddress((void**)&qpk,  g_qpk);
    cudaGetSymbolAddress((void**)&bpk,  g_bpk);
    cudaGetSymbolAddress((void**)&dpk1, g_dpk1);
    cudaGetSymbolAddress((void**)&dpk2, g_dpk2);

    int condSm  = (NMEL * (Tmel + 8) + NMEL * NMEL * 4) * 4;
    int blockSm = (RC + RC + NMEL + RC) * TT * 4;   // 225280
    int d1Sm    = SC * TT * 4;                      // 122880
    int d2Sm    = NQ * TT * 4;                      // 131072

    cudaFuncSetAttribute(cond_kernel,  cudaFuncAttributeMaxDynamicSharedMemorySize, condSm);
    cudaFuncSetAttribute(block_kernel, cudaFuncAttributeMaxDynamicSharedMemorySize, blockSm);
    cudaFuncSetAttribute(dense_kernel, cudaFuncAttributeMaxDynamicSharedMemorySize, d2Sm);

    int nT = (L + TT - 1) / TT;

    int packTot = NB * 120 * 120 + NB * 120 * 40 + NB * 180 * 120 + 128 * 240 + 128 * 256;
    prepack_kernel<<<(packTot + 255) / 256, 256>>>(bcw, bqw, bsw, brw, h1w, h2w,
                                                   wpk, qpk, bpk, dpk1, dpk2);
    cond_kernel<<<HOP, 256, condSm>>>(mel, up_w, up_b, cond, L, Tmel);
    init_kernel<<<(RC * L + 255) / 256, 256>>>(wav, in_w, in_b, res0, L);

    const int dils[NB] = {1, 2, 4, 8, 16, 32, 64, 128, 1, 2, 4, 8, 16, 32, 64, 128};
    for (int i = 0; i < NB; i++) {
        const float* rin = (i & 1) ? res1 : res0;
        float* rout = (i & 1) ? res0 : res1;
        block_kernel<<<nT, NTH, blockSm>>>(rin, rout, skip, cond,
                                           (const float*)(wpk + (size_t)i * 120 * 120),
                                           (const float*)(qpk + (size_t)i * 120 * 40),
                                           (const float*)(bpk + (size_t)i * 192 * 120),
                                           bcb + i * SC, bqb + i * SC,
                                           bsb + i * SC, brb + i * RC,
                                           dils[i], L, (i == 0) ? 1 : 0, (i != NB - 1) ? 1 : 0);
    }

    dense_kernel<<<nT, NTH, d1Sm>>>(skip, (const float*)dpk1, h1b, yb, L, SC, NQ, 1, 1);
    dense_kernel<<<nT, NTH, d2Sm>>>(yb, (const float*)dpk2, h2b, out, L, NQ, NQ, 0, 0);
    (void)n_in; (void)out_size;
}

// round 15
// speedup vs baseline: 1.0567x; 1.0567x over previous
#include <cuda_runtime.h>
#include <cuda_bf16.h>

#define HOP   256
#define KUP   800
#define NMEL  80
#define RC    120
#define SC    240
#define NQ    256
#define NB    16
#define MAXL  40960
#define TT    128
#define NTH   512

// Scratch (device-global: sanctioned alternative to cudaMalloc)
static __device__ float g_cond[NMEL * MAXL];
static __device__ float g_res0[RC * MAXL];
static __device__ float g_res1[RC * MAXL];
static __device__ float g_skip[SC * MAXL];
static __device__ float g_y[NQ * MAXL];
// Pre-packed weights
static __device__ float4 g_wpk[NB * 120 * 120];   // (wt0,ws0,wt1,ws1) per (layer,pair,c)
static __device__ float4 g_qpk[NB * 120 * 40];    // (qt[c],qs[c],qt[c+1],qs[c+1])
static __device__ float2 g_bpk[NB * 192 * 120];   // (w_row2k[c], w_row2k+1[c]) pad 192
static __device__ float2 g_dpk1[128 * 240];       // h1 row-pairs
static __device__ float2 g_dpk2[128 * 256];       // h2 row-pairs

typedef unsigned long long ull;

// ---------------- packed f32x2 helpers (PTX-only FFMA2 path) ----------------
__device__ __forceinline__ ull pk2(float x, float y) {
    ull r;
    asm("mov.b64 %0, {%1,%2};" : "=l"(r) : "f"(x), "f"(y));
    return r;
}
__device__ __forceinline__ ull fma2(ull a, ull b, ull c) {
    ull d;
    asm("fma.rn.f32x2 %0, %1, %2, %3;" : "=l"(d) : "l"(a), "l"(b), "l"(c));
    return d;
}
__device__ __forceinline__ float2 up2(ull v) {
    float2 f;
    asm("mov.b64 {%0,%1}, %2;" : "=f"(f.x), "=f"(f.y) : "l"(v));
    return f;
}
__device__ __forceinline__ float gate(float zt, float zs) {
    return tanhf(zt) * (1.f / (1.f + __expf(-zs)));
}
// load 4 consecutive t from row base (16B aligned) and make 4 splats
__device__ __forceinline__ void splat4(ull* dst, const float* base) {
    float4 v = *(const float4*)base;
    dst[0] = pk2(v.x, v.x);
    dst[1] = pk2(v.y, v.y);
    dst[2] = pk2(v.z, v.z);
    dst[3] = pk2(v.w, v.w);
}

// --- compute halves (consume pre-loaded weight registers) ---
// Phase A causal: channels cc, cc+1; w0[j]=(wt0,ws0|wt1... per chan cc), w1[j]=chan cc+1
__device__ __forceinline__ void halfA(ull z[4][4], const float* sA, const float* sB,
                                      int cc, int tl,
                                      const ulonglong2* w0, const ulonglong2* w1) {
    ull A[4], B[4];
    splat4(A, &sA[cc * TT + tl]);
    splat4(B, &sB[cc * TT + tl]);
    #pragma unroll
    for (int j = 0; j < 4; j++) {
        #pragma unroll
        for (int k = 0; k < 4; k++) {
            z[j][k] = fma2(w0[j].x, A[k], z[j][k]);
            z[j][k] = fma2(w0[j].y, B[k], z[j][k]);
        }
    }
    splat4(A, &sA[(cc + 1) * TT + tl]);
    splat4(B, &sB[(cc + 1) * TT + tl]);
    #pragma unroll
    for (int j = 0; j < 4; j++) {
        #pragma unroll
        for (int k = 0; k < 4; k++) {
            z[j][k] = fma2(w1[j].x, A[k], z[j][k]);
            z[j][k] = fma2(w1[j].y, B[k], z[j][k]);
        }
    }
}
// single-plane half (cond / phaseB / dense): w[j].x = chan cc, w[j].y = chan cc+1
__device__ __forceinline__ void halfS(ull z[4][4], const float* sX,
                                      int cc, int tl, const ulonglong2* w) {
    ull C[4];
    splat4(C, &sX[cc * TT + tl]);
    #pragma unroll
    for (int j = 0; j < 4; j++) {
        #pragma unroll
        for (int k = 0; k < 4; k++)
            z[j][k] = fma2(w[j].x, C[k], z[j][k]);
    }
    splat4(C, &sX[(cc + 1) * TT + tl]);
    #pragma unroll
    for (int j = 0; j < 4; j++) {
        #pragma unroll
        for (int k = 0; k < 4; k++)
            z[j][k] = fma2(w[j].y, C[k], z[j][k]);
    }
}

// ---------------- weight pre-pack -----------------------------------------------
__global__ void prepack_kernel(const float* __restrict__ bcw, const float* __restrict__ bqw,
                               const float* __restrict__ bsw, const float* __restrict__ brw,
                               const float* __restrict__ h1w, const float* __restrict__ h2w,
                               float4* __restrict__ wpk, float4* __restrict__ qpk,
                               float2* __restrict__ bpk, float2* __restrict__ dpk1,
                               float2* __restrict__ dpk2) {
    int idx = blockIdx.x * blockDim.x + threadIdx.x;
    const int W4 = NB * 120 * 120, Q4 = NB * 120 * 40, B2 = NB * 180 * 120;
    const int D1 = 128 * 240, D2 = 128 * 256;
    if (idx < W4) {
        int i = idx / (120 * 120), r = idx % (120 * 120), p = r / 120, c = r % 120;
        const float* cw = bcw + (size_t)i * SC * RC * 2;
        wpk[((size_t)i * 120 + p) * 120 + c] = make_float4(
            cw[(p * RC + c) * 2],     cw[((p + RC) * RC + c) * 2],
            cw[(p * RC + c) * 2 + 1], cw[((p + RC) * RC + c) * 2 + 1]);
    } else if (idx < W4 + Q4) {
        int k = idx - W4;
        int i = k / (120 * 40), r = k % (120 * 40), p = r / 40, cc = r % 40, c = cc * 2;
        const float* qw = bqw + (size_t)i * SC * NMEL;
        qpk[((size_t)i * 120 + p) * 40 + cc] = make_float4(
            qw[p * NMEL + c],     qw[(p + RC) * NMEL + c],
            qw[p * NMEL + c + 1], qw[(p + RC) * NMEL + c + 1]);
    } else if (idx < W4 + Q4 + B2) {
        int k = idx - W4 - Q4;
        int i = k / (180 * 120), r = k % (180 * 120), pr = r / 120, c = r % 120;
        float2 v;
        if (pr < 120) {
            const float* sw = bsw + (size_t)i * SC * RC;
            v = make_float2(sw[(2 * pr) * RC + c], sw[(2 * pr + 1) * RC + c]);
        } else {
            const float* rw = brw + (size_t)i * RC * RC;
            int q = pr - 120;
            v = make_float2(rw[(2 * q) * RC + c], rw[(2 * q + 1) * RC + c]);
        }
        bpk[((size_t)i * 192 + pr) * 120 + c] = v;
    } else if (idx < W4 + Q4 + B2 + D1) {
        int k = idx - W4 - Q4 - B2;
        int p = k / 240, c = k % 240;
        dpk1[p * 240 + c] = make_float2(h1w[(2 * p) * SC + c], h1w[(2 * p + 1) * SC + c]);
    } else if (idx < W4 + Q4 + B2 + D1 + D2) {
        int k = idx - W4 - Q4 - B2 - D1;
        int p = k / 256, c = k % 256;
        dpk2[p * 256 + c] = make_float2(h2w[(2 * p) * NQ + c], h2w[(2 * p + 1) * NQ + c]);
    }
}

// ---------------- cond upsampling: phase-major transposed conv ----------------
__global__ __launch_bounds__(256, 1)
void cond_kernel(const float* __restrict__ mel,
                 const float* __restrict__ upw,
                 const float* __restrict__ upb,
                 float* __restrict__ cond,
                 int L, int Tmel) {
    extern __shared__ float sm[];
    const int MS = Tmel + 8;
    float* smel = sm;
    float* sw   = sm + NMEL * MS;
    int tid = threadIdx.x;
    int p  = blockIdx.x;
    int k0 = 255 - p;

    for (int idx = tid; idx < NMEL * MS; idx += 256) {
        int c = idx / MS, col = idx - c * MS;
        smel[idx] = (col < Tmel) ? mel[c * Tmel + col] : 0.f;
    }
    for (int idx = tid; idx < NMEL * NMEL * 4; idx += 256) {
        int j = idx & 3;
        int oc = idx >> 2;
        int k = k0 + 256 * j;
        sw[idx] = (k < KUP) ? upw[oc * KUP + k] : 0.f;
    }
    __syncthreads();

    int nI = (L - p + 255) >> 8;
    int tx = tid & 7;
    int gy = tid >> 3;
    for (int o = gy; o < NMEL; o += 32) {
        float b = upb[o];
        for (int ib = 0; ib < nI; ib += 32) {
            int i0 = ib + tx * 4;
            float a0 = b, a1 = b, a2 = b, a3 = b;
            for (int c = 0; c < NMEL; c++) {
                const float4 w = *(const float4*)&sw[(o * NMEL + c) << 2];
                const float* mp = &smel[c * MS + i0 + 1];
                float m0 = mp[0], m1 = mp[1], m2 = mp[2], m3 = mp[3];
                float m4 = mp[4], m5 = mp[5], m6 = mp[6];
                a0 += w.x * m0 + w.y * m1 + w.z * m2 + w.w * m3;
                a1 += w.x * m1 + w.y * m2 + w.z * m3 + w.w * m4;
                a2 += w.x * m2 + w.y * m3 + w.z * m4 + w.w * m5;
                a3 += w.x * m3 + w.y * m4 + w.z * m5 + w.w * m6;
            }
            int t = p + (i0 << 8);
            if (i0     < nI) cond[o * L + t]       = a0;
            if (i0 + 1 < nI) cond[o * L + t + 256] = a1;
            if (i0 + 2 < nI) cond[o * L + t + 512] = a2;
            if (i0 + 3 < nI) cond[o * L + t + 768] = a3;
        }
    }
}

// ---------------- input 1x1 conv ----------------------------------------------
__global__ void init_kernel(const float* __restrict__ wav,
                            const float* __restrict__ inw,
                            const float* __restrict__ inb,
                            float* __restrict__ res, int L) {
    int idx = blockIdx.x * blockDim.x + threadIdx.x;
    if (idx >= RC * L) return;
    int c = idx / L, t = idx - c * L;
    res[idx] = inw[c] * wav[t] + inb[c];
}

// ---------------- fused WaveNet block: pipelined weight loads -------------------
__global__ __launch_bounds__(NTH, 1)
void block_kernel(const float* __restrict__ rin,
                  float* __restrict__ rout,
                  float* __restrict__ skip,
                  const float* __restrict__ cond,
                  const float* __restrict__ wpk,  // [120][120][4]
                  const float* __restrict__ qpk,  // [120][40][4]
                  const float* __restrict__ bpk,  // [192][120][2]
                  const float* __restrict__ cb,
                  const float* __restrict__ qb,
                  const float* __restrict__ sbv,
                  const float* __restrict__ rb,
                  int d, int L, int first, int wres) {
    extern __shared__ float sm[];
    float* sA = sm;                 // res[c][t-d]  [120][128]
    float* sB = sA + RC * TT;       // res[c][t]    [120][128]
    float* sC = sB + RC * TT;       // cond[c][t]   [80][128]
    float* sH = sC + NMEL * TT;     // h[c][t]      [120][128]

    int tid = threadIdx.x;
    int t0 = blockIdx.x * TT;

    for (int idx = tid; idx < RC * TT; idx += NTH) {
        int c = idx >> 7, tl0 = idx & 127;
        int t = t0 + tl0;
        float vb = 0.f, va = 0.f;
        if (t < L) {
            vb = rin[c * L + t];
            int ta = t - d;
            if (ta >= 0) va = rin[c * L + ta];
        }
        sB[idx] = vb;
        sA[idx] = va;
    }
    for (int idx = tid; idx < NMEL * TT; idx += NTH) {
        int c = idx >> 7, tl0 = idx & 127;
        int t = t0 + tl0;
        sC[idx] = (t < L) ? cond[c * L + t] : 0.f;
    }
    __syncthreads();

    const int lid = tid & 31;
    const int wid = tid >> 5;    // 0..15
    const int tl  = 4 * lid;

    // ---- Phase A: 2 passes x 4 gate-pairs/warp, pipelined weights ----
    #pragma unroll 1
    for (int pass = 0; pass < 2; pass++) {
        const int p0 = pass * 64 + wid * 4;
        if (p0 >= RC) break;
        const float* wrow[4];
        const float* qrow[4];
        ull z[4][4];
        #pragma unroll
        for (int j = 0; j < 4; j++) {
            int p = p0 + j < RC ? p0 + j : RC - 1;
            wrow[j] = wpk + (size_t)p * 480;
            qrow[j] = qpk + (size_t)p * 160;
            ull b0 = pk2(cb[p] + qb[p], cb[p + RC] + qb[p + RC]);
            z[j][0] = b0; z[j][1] = b0; z[j][2] = b0; z[j][3] = b0;
        }
        // causal part: K=120 channels, step 4, double-buffered
        {
            ulonglong2 wA0[4], wA1[4], wB0[4], wB1[4];
            #pragma unroll
            for (int j = 0; j < 4; j++) {
                wA0[j] = *(const ulonglong2*)(wrow[j]);
                wA1[j] = *(const ulonglong2*)(wrow[j] + 4);
            }
            #pragma unroll 1
            for (int c = 0; c < RC; c += 4) {
                #pragma unroll
                for (int j = 0; j < 4; j++) {
                    const float* wr = wrow[j] + 4 * (c + 2);
                    wB0[j] = *(const ulonglong2*)wr;
                    wB1[j] = *(const ulonglong2*)(wr + 4);
                }
                halfA(z, sA, sB, c, tl, wA0, wA1);
                int c4 = (c + 4 < RC) ? c + 4 : 0;
                #pragma unroll
                for (int j = 0; j < 4; j++) {
                    const float* wr = wrow[j] + 4 * c4;
                    wA0[j] = *(const ulonglong2*)wr;
                    wA1[j] = *(const ulonglong2*)(wr + 4);
                }
                halfA(z, sA, sB, c + 2, tl, wB0, wB1);
            }
        }
        // cond part: K=80 channels, step 4, double-buffered
        {
            ulonglong2 qA[4], qB[4];
            #pragma unroll
            for (int j = 0; j < 4; j++)
                qA[j] = *(const ulonglong2*)(qrow[j]);
            #pragma unroll 1
            for (int c = 0; c < NMEL; c += 4) {
                #pragma unroll
                for (int j = 0; j < 4; j++)
                    qB[j] = *(const ulonglong2*)(qrow[j] + 2 * (c + 2));
                halfS(z, sC, c, tl, qA);
                int c4 = (c + 4 < NMEL) ? c + 4 : 0;
                #pragma unroll
                for (int j = 0; j < 4; j++)
                    qA[j] = *(const ulonglong2*)(qrow[j] + 2 * c4);
                halfS(z, sC, c + 2, tl, qB);
            }
        }
        #pragma unroll
        for (int j = 0; j < 4; j++) {
            if (p0 + j >= RC) break;
            float4 h;
            float2 g0 = up2(z[j][0]);
            float2 g1 = up2(z[j][1]);
            float2 g2 = up2(z[j][2]);
            float2 g3 = up2(z[j][3]);
            h.x = gate(g0.x, g0.y);
            h.y = gate(g1.x, g1.y);
            h.z = gate(g2.x, g2.y);
            h.w = gate(g3.x, g3.y);
            *(float4*)&sH[(p0 + j) * TT + tl] = h;
        }
    }
    __syncthreads();

    // ---- Phase B: 3 passes x 4 row-pairs/warp, pipelined weights ----
    #pragma unroll 1
    for (int pass = 0; pass < 3; pass++) {
        const int k0 = pass * 64 + wid * 4;
        if (k0 >= 180) break;
        const float* brow[4];
        ull z2[4][4];
        #pragma unroll
        for (int j = 0; j < 4; j++) {
            int k = k0 + j;
            int kk = k < 180 ? k : 179;
            brow[j] = bpk + (size_t)kk * 240;
            float b1, b2;
            if (kk < 120) { b1 = sbv[2 * kk]; b2 = sbv[2 * kk + 1]; }
            else { b1 = rb[2 * (kk - 120)]; b2 = rb[2 * (kk - 120) + 1]; }
            ull bb = pk2(b1, b2);
            z2[j][0] = bb; z2[j][1] = bb; z2[j][2] = bb; z2[j][3] = bb;
        }
        {
            ulonglong2 bA[4], bB[4];
            #pragma unroll
            for (int j = 0; j < 4; j++)
                bA[j] = *(const ulonglong2*)(brow[j]);
            #pragma unroll 1
            for (int c = 0; c < RC; c += 4) {
                #pragma unroll
                for (int j = 0; j < 4; j++)
                    bB[j] = *(const ulonglong2*)(brow[j] + 2 * (c + 2));
                halfS(z2, sH, c, tl, bA);
                int c4 = (c + 4 < RC) ? c + 4 : 0;
                #pragma unroll
                for (int j = 0; j < 4; j++)
                    bA[j] = *(const ulonglong2*)(brow[j] + 2 * c4);
                halfS(z2, sH, c + 2, tl, bB);
            }
        }
        int t = t0 + tl;
        #pragma unroll
        for (int j = 0; j < 4; j++) {
            int k = k0 + j;
            if (k >= 180) break;
            float2 v0 = up2(z2[j][0]);
            float2 v1 = up2(z2[j][1]);
            float2 v2 = up2(z2[j][2]);
            float2 v3 = up2(z2[j][3]);
            float4 o1 = make_float4(v0.x, v1.x, v2.x, v3.x);  // row 2k, t..t+3
            float4 o2 = make_float4(v0.y, v1.y, v2.y, v3.y);  // row 2k+1
            if (k < 120) {
                int r1 = 2 * k;
                float* d1 = &skip[(size_t)r1 * L + t];
                float* d2 = &skip[(size_t)(r1 + 1) * L + t];
                if (t + 3 < L) {
                    if (first) { *(float4*)d1 = o1; *(float4*)d2 = o2; }
                    else {
                        float4 p1 = *(const float4*)d1, p2 = *(const float4*)d2;
                        o1.x += p1.x; o1.y += p1.y; o1.z += p1.z; o1.w += p1.w;
                        o2.x += p2.x; o2.y += p2.y; o2.z += p2.z; o2.w += p2.w;
                        *(float4*)d1 = o1; *(float4*)d2 = o2;
                    }
                } else {
                    float ov1[4] = {o1.x, o1.y, o1.z, o1.w};
                    float ov2[4] = {o2.x, o2.y, o2.z, o2.w};
                    #pragma unroll
                    for (int e = 0; e < 4; e++)
                        if (t + e < L) {
                            d1[e] = first ? ov1[e] : d1[e] + ov1[e];
                            d2[e] = first ? ov2[e] : d2[e] + ov2[e];
                        }
                }
            } else if (wres) {
                int rr = 2 * (k - 120);
                float4 s1 = *(const float4*)&sB[rr * TT + tl];
                float4 s2 = *(const float4*)&sB[(rr + 1) * TT + tl];
                o1.x += s1.x; o1.y += s1.y; o1.z += s1.z; o1.w += s1.w;
                o2.x += s2.x; o2.y += s2.y; o2.z += s2.z; o2.w += s2.w;
                float* d1 = &rout[(size_t)rr * L + t];
                float* d2 = &rout[(size_t)(rr + 1) * L + t];
                if (t + 3 < L) {
                    *(float4*)d1 = o1;
                    *(float4*)d2 = o2;
                } else {
                    float ov1[4] = {o1.x, o1.y, o1.z, o1.w};
                    float ov2[4] = {o2.x, o2.y, o2.z, o2.w};
                    #pragma unroll
                    for (int e = 0; e < 4; e++)
                        if (t + e < L) { d1[e] = ov1[e]; d2[e] = ov2[e]; }
                }
            }
        }
    }
}

// ---------------- dense head: pipelined weights ---------------------------------
__global__ __launch_bounds__(NTH, 1)
void dense_kernel(const float* __restrict__ x,
                  const float* __restrict__ dpk,  // [M/2][K][2]
                  const float* __restrict__ b,
                  float* __restrict__ out,
                  int L, int K, int M, int relu_in, int relu_out) {
    extern __shared__ float sm[];
    float* sX = sm;   // [K][128]
    int tid = threadIdx.x;
    int t0 = blockIdx.x * TT;
    for (int idx = tid; idx < K * TT; idx += NTH) {
        int c = idx >> 7, tl0 = idx & 127;
        int t = t0 + tl0;
        float v = (t < L) ? x[c * L + t] : 0.f;
        sX[idx] = relu_in ? fmaxf(v, 0.f) : v;
    }
    __syncthreads();

    const int lid = tid & 31;
    const int wid = tid >> 5;
    const int tl  = 4 * lid;
    const int MP = M / 2;   // pairs (128)

    #pragma unroll 1
    for (int pass = 0; pass * 64 < MP; pass++) {
        const int k0 = pass * 64 + wid * 4;
        if (k0 >= MP) break;
        const float* drow[4];
        ull z[4][4];
        #pragma unroll
        for (int j = 0; j < 4; j++) {
            int k = k0 + j;
            int kk = k < MP ? k : MP - 1;
            drow[j] = dpk + (size_t)kk * K * 2;
            ull bb = pk2(b[2 * kk], b[2 * kk + 1]);
            z[j][0] = bb; z[j][1] = bb; z[j][2] = bb; z[j][3] = bb;
        }
        {
            ulonglong2 dA[4], dB[4];
            #pragma unroll
            for (int j = 0; j < 4; j++)
                dA[j] = *(const ulonglong2*)(drow[j]);
            #pragma unroll 1
            for (int c = 0; c < K; c += 4) {
                #pragma unroll
                for (int j = 0; j < 4; j++)
                    dB[j] = *(const ulonglong2*)(drow[j] + 2 * (c + 2));
                halfS(z, sX, c, tl, dA);
                int c4 = (c + 4 < K) ? c + 4 : 0;
                #pragma unroll
                for (int j = 0; j < 4; j++)
                    dA[j] = *(const ulonglong2*)(drow[j] + 2 * c4);
                halfS(z, sX, c + 2, tl, dB);
            }
        }
        int t = t0 + tl;
        #pragma unroll
        for (int j = 0; j < 4; j++) {
            int k = k0 + j;
            if (k >= MP) break;
            float2 v0 = up2(z[j][0]);
            float2 v1 = up2(z[j][1]);
            float2 v2 = up2(z[j][2]);
            float2 v3 = up2(z[j][3]);
            float4 o1 = make_float4(v0.x, v1.x, v2.x, v3.x);
            float4 o2 = make_float4(v0.y, v1.y, v2.y, v3.y);
            if (relu_out) {
                o1.x = fmaxf(o1.x, 0.f); o1.y = fmaxf(o1.y, 0.f);
                o1.z = fmaxf(o1.z, 0.f); o1.w = fmaxf(o1.w, 0.f);
                o2.x = fmaxf(o2.x, 0.f); o2.y = fmaxf(o2.y, 0.f);
                o2.z = fmaxf(o2.z, 0.f); o2.w = fmaxf(o2.w, 0.f);
            }
            float* d1 = &out[(size_t)(2 * k) * L + t];
            float* d2 = &out[(size_t)(2 * k + 1) * L + t];
            if (t + 3 < L) {
                *(float4*)d1 = o1;
                *(float4*)d2 = o2;
            } else {
                float ov1[4] = {o1.x, o1.y, o1.z, o1.w};
                float ov2[4] = {o2.x, o2.y, o2.z, o2.w};
                #pragma unroll
                for (int e = 0; e < 4; e++)
                    if (t + e < L) { d1[e] = ov1[e]; d2[e] = ov2[e]; }
            }
        }
    }
}

// ---------------- host launch ---------------------------------------------------
extern "C" void kernel_launch(void* const* d_in, const int* in_sizes, int n_in,
                              void* d_out, int out_size) {
    const float* wav  = (const float*)d_in[0];
    const float* mel  = (const float*)d_in[1];
    const float* up_w = (const float*)d_in[2];
    const float* up_b = (const float*)d_in[3];
    const float* in_w = (const float*)d_in[4];
    const float* in_b = (const float*)d_in[5];
    const float* bcw  = (const float*)d_in[6];
    const float* bcb  = (const float*)d_in[7];
    const float* bqw  = (const float*)d_in[8];
    const float* bqb  = (const float*)d_in[9];
    const float* bsw  = (const float*)d_in[10];
    const float* bsb  = (const float*)d_in[11];
    const float* brw  = (const float*)d_in[12];
    const float* brb  = (const float*)d_in[13];
    const float* h1w  = (const float*)d_in[14];
    const float* h1b  = (const float*)d_in[15];
    const float* h2w  = (const float*)d_in[16];
    const float* h2b  = (const float*)d_in[17];
    float* out = (float*)d_out;

    int wav_len = in_sizes[0];
    int Tmel = in_sizes[1] / NMEL;
    int up_len = (Tmel - 1) * HOP + 1;
    int pad = KUP - 1 - (KUP + 4 * HOP - 1024);   // = -1
    int cond_len = up_len + 2 * pad - KUP + 1;
    int L = wav_len < cond_len ? wav_len : cond_len;
    if (L > MAXL) L = MAXL;

    float *cond, *res0, *res1, *skip, *yb;
    float4 *wpk, *qpk; float2 *bpk, *dpk1, *dpk2;
    cudaGetSymbolAddress((void**)&cond, g_cond);
    cudaGetSymbolAddress((void**)&res0, g_res0);
    cudaGetSymbolAddress((void**)&res1, g_res1);
    cudaGetSymbolAddress((void**)&skip, g_skip);
    cudaGetSymbolAddress((void**)&yb,   g_y);
    cudaGetSymbolAddress((void**)&wpk,  g_wpk);
    cudaGetSymbolAddress((void**)&qpk,  g_qpk);
    cudaGetSymbolAddress((void**)&bpk,  g_bpk);
    cudaGetSymbolAddress((void**)&dpk1, g_dpk1);
    cudaGetSymbolAddress((void**)&dpk2, g_dpk2);

    int condSm  = (NMEL * (Tmel + 8) + NMEL * NMEL * 4) * 4;
    int blockSm = (RC + RC + NMEL + RC) * TT * 4;   // 225280
    int d1Sm    = SC * TT * 4;                      // 122880
    int d2Sm    = NQ * TT * 4;                      // 131072

    cudaFuncSetAttribute(cond_kernel,  cudaFuncAttributeMaxDynamicSharedMemorySize, condSm);
    cudaFuncSetAttribute(block_kernel, cudaFuncAttributeMaxDynamicSharedMemorySize, blockSm);
    cudaFuncSetAttribute(dense_kernel, cudaFuncAttributeMaxDynamicSharedMemorySize, d2Sm);

    int nT = (L + TT - 1) / TT;

    int packTot = NB * 120 * 120 + NB * 120 * 40 + NB * 180 * 120 + 128 * 240 + 128 * 256;
    prepack_kernel<<<(packTot + 255) / 256, 256>>>(bcw, bqw, bsw, brw, h1w, h2w,
                                                   wpk, qpk, bpk, dpk1, dpk2);
    cond_kernel<<<HOP, 256, condSm>>>(mel, up_w, up_b, cond, L, Tmel);
    init_kernel<<<(RC * L + 255) / 256, 256>>>(wav, in_w, in_b, res0, L);

    const int dils[NB] = {1, 2, 4, 8, 16, 32, 64, 128, 1, 2, 4, 8, 16, 32, 64, 128};
    for (int i = 0; i < NB; i++) {
        const float* rin = (i & 1) ? res1 : res0;
        float* rout = (i & 1) ? res0 : res1;
        block_kernel<<<nT, NTH, blockSm>>>(rin, rout, skip, cond,
                                           (const float*)(wpk + (size_t)i * 120 * 120),
                                           (const float*)(qpk + (size_t)i * 120 * 40),
                                           (const float*)(bpk + (size_t)i * 192 * 120),
                                           bcb + i * SC, bqb + i * SC,
                                           bsb + i * SC, brb + i * RC,
                                           dils[i], L, (i == 0) ? 1 : 0, (i != NB - 1) ? 1 : 0);
    }

    dense_kernel<<<nT, NTH, d1Sm>>>(skip, (const float*)dpk1, h1b, yb, L, SC, NQ, 1, 1);
    dense_kernel<<<nT, NTH, d2Sm>>>(yb, (const float*)dpk2, h2b, out, L, NQ, NQ, 0, 0);
    (void)n_in; (void)out_size;
}